// round 13
// baseline (speedup 1.0000x reference)
#include <cuda_runtime.h>
#include <cuda_fp16.h>
#include <cstdint>

#define BS   4
#define NN   2048
#define CIN  128
#define COUT 64
#define H    4
#define HD   256
#define TI   64
#define TJ   64
#define JH   1024
#define NJT  16
#define LOG2E 1.4426950408889634f

// device scratch (allocation-free)
__device__ __half g_hs_h[(size_t)BS * H * COUT * NN];  // [bh][d][n] fp16 (transposed)
__device__ __half g_whi[HD * CIN];                     // [m=256][k=128] hi
__device__ __half g_wlo[HD * CIN];                     // [m=256][k=128] lo
__device__ float g_el[BS * H * NN];                    // pre-scaled by log2e
__device__ float g_er[BS * H * NN];                    // pre-scaled by log2e
__device__ unsigned int g_emax_key[BS * H];            // float-ordered key
__device__ float g_wl[CIN * H];
__device__ float g_wr[CIN * H];
__device__ float g_opart[2][(size_t)BS * NN * HD];
__device__ float g_lpart[2][BS * H * NN];

// K2 smem layout (R7/R12)
#define PSTR 72
#define PBUF_BYTES  9216
#define HSBUF_BYTES 10368
#define OFF_HS_BYTES 18432
#define OFF_ER_F 9792          // per buf {er[64],B[64],D[64]} x2
#define OFF_EL_F 10176         // per head {el[64],A[64],C[64]} x4
#define SMEM_K2 44032

__device__ __forceinline__ uint32_t smem_u32(const void* p) {
    uint32_t a;
    asm("{ .reg .u64 t; cvta.to.shared.u64 t, %1; cvt.u32.u64 %0, t; }" : "=r"(a) : "l"(p));
    return a;
}
__device__ __forceinline__ float ex2f(float x) {
    float r;
    asm("ex2.approx.f32 %0, %1;" : "=f"(r) : "f"(x));
    return r;
}
__device__ __forceinline__ unsigned int fenc(float f) {
    unsigned int b = __float_as_uint(f);
    return (b & 0x80000000u) ? ~b : (b | 0x80000000u);
}
__device__ __forceinline__ float fdec(unsigned int k) {
    unsigned int b = (k & 0x80000000u) ? (k ^ 0x80000000u) : ~k;
    return __uint_as_float(b);
}
__device__ __forceinline__ void mma_f16(float* d, const uint32_t* a, const uint32_t* b) {
    asm volatile(
        "mma.sync.aligned.m16n8k16.row.col.f32.f16.f16.f32 "
        "{%0,%1,%2,%3}, {%4,%5,%6,%7}, {%8,%9}, {%0,%1,%2,%3};"
        : "+f"(d[0]), "+f"(d[1]), "+f"(d[2]), "+f"(d[3])
        : "r"(a[0]), "r"(a[1]), "r"(a[2]), "r"(a[3]), "r"(b[0]), "r"(b[1]));
}
__device__ __forceinline__ void ldsm_x4(uint32_t* r, uint32_t addr) {
    asm volatile("ldmatrix.sync.aligned.m8n8.x4.shared.b16 {%0,%1,%2,%3}, [%4];"
                 : "=r"(r[0]), "=r"(r[1]), "=r"(r[2]), "=r"(r[3]) : "r"(addr));
}
__device__ __forceinline__ void ldsm_x2(uint32_t* r, uint32_t addr) {
    asm volatile("ldmatrix.sync.aligned.m8n8.x2.shared.b16 {%0,%1}, [%2];"
                 : "=r"(r[0]), "=r"(r[1]) : "r"(addr));
}
__device__ __forceinline__ void cp16(uint32_t dst, const void* src) {
    asm volatile("cp.async.ca.shared.global [%0], [%1], 16;" :: "r"(dst), "l"(src));
}
#define CP_COMMIT asm volatile("cp.async.commit_group;" ::: "memory")
#define CP_WAIT0  asm volatile("cp.async.wait_group 0;" ::: "memory")
#define BARS(id, n) asm volatile("bar.sync %0, %1;" :: "r"(id), "r"(n) : "memory")
#define BARA(id, n) asm volatile("bar.arrive %0, %1;" :: "r"(id), "r"(n) : "memory")

// ---------------- K0w: W1 -> hi/lo fp16 [m][k]; wl/wr; reset emax ----------------
__global__ __launch_bounds__(256) void k0w(const float* __restrict__ W1,
                                           const float* __restrict__ a_l,
                                           const float* __restrict__ a_r) {
    const int blk = blockIdx.x, tid = threadIdx.x;
    if (blk < 32) {
        int idx = blk * 1024 + tid * 4;
        int k = idx >> 8, m = idx & 255;
        float4 w4 = *(const float4*)(W1 + (size_t)k * HD + m);
        const float* we = (const float*)&w4;
        #pragma unroll
        for (int e = 0; e < 4; e++) {
            __half hi = __float2half_rn(we[e]);
            g_whi[(m + e) * CIN + k] = hi;
            g_wlo[(m + e) * CIN + k] = __float2half_rn(we[e] - __half2float(hi));
        }
    } else {
        const int lr = blk - 32;                 // 0 = wl, 1 = wr
        if (lr == 0 && tid < BS * H) g_emax_key[tid] = 0u;
        const float* av = lr ? a_r : a_l;
        #pragma unroll
        for (int t = 0; t < 2; t++) {
            int e = tid + t * 256;               // 0..511
            int k = e >> 2, h = e & 3;
            float s = 0.f;
            for (int d = 0; d < COUT; d++)
                s += __ldg(W1 + (size_t)k * HD + h * COUT + d) * __ldg(av + d);
            if (lr) g_wr[k * H + h] = s; else g_wl[k * H + h] = s;
        }
    }
}

// ---------------- K0b: el/er = xs @ wl/wr (fp32), emax via atomic keys ----------------
__global__ __launch_bounds__(256) void k0b_elr(const float* __restrict__ xs) {
    __shared__ float swl[CIN * H];
    __shared__ float swr[CIN * H];
    __shared__ float sred[256];
    const int tid = threadIdx.x;
    const int row = blockIdx.x * 256 + tid;
    const int b = row >> 11, i = row & (NN - 1);

    swl[tid] = g_wl[tid]; swl[tid + 256] = g_wl[tid + 256];
    swr[tid] = g_wr[tid]; swr[tid + 256] = g_wr[tid + 256];
    __syncthreads();

    const float4* xr = (const float4*)(xs + (size_t)row * CIN);
    float el[H] = {}, er[H] = {};
    #pragma unroll 8
    for (int q = 0; q < 32; q++) {
        float4 x = xr[q];
        const float* xe = (const float*)&x;
        #pragma unroll
        for (int e = 0; e < 4; e++) {
            int k = q * 4 + e;
            float4 wl4 = *(const float4*)(swl + k * H);
            float4 wr4 = *(const float4*)(swr + k * H);
            el[0] += xe[e] * wl4.x; el[1] += xe[e] * wl4.y;
            el[2] += xe[e] * wl4.z; el[3] += xe[e] * wl4.w;
            er[0] += xe[e] * wr4.x; er[1] += xe[e] * wr4.y;
            er[2] += xe[e] * wr4.z; er[3] += xe[e] * wr4.w;
        }
    }
    float ers[H];
    #pragma unroll
    for (int h = 0; h < H; h++) {
        const int bh = b * H + h;
        g_el[(size_t)bh * NN + i] = el[h] * LOG2E;
        ers[h] = er[h] * LOG2E;
        g_er[(size_t)bh * NN + i] = ers[h];
    }
    #pragma unroll
    for (int h = 0; h < H; h++) {
        __syncthreads();
        sred[tid] = ers[h];
        __syncthreads();
        for (int s = 128; s > 0; s >>= 1) {
            if (tid < s) sred[tid] = fmaxf(sred[tid], sred[tid + s]);
            __syncthreads();
        }
        if (tid == 0) atomicMax(&g_emax_key[b * H + h], fenc(sred[0]));
    }
}

// ---------------- K1h: hsT = W1^T @ xs^T, full W resident in smem ----------------
// smem (halfs): xs hi [64][136], xs lo [64][136], W hi [256][136], W lo [256][136]
#define XHI_H 0
#define XLO_H 8704
#define WHI_H 17408
#define WLO_H 52224
#define SMEM_K1H ((WLO_H + 256 * 136) * 2)   // 174080 B

__global__ __launch_bounds__(256) void k1h_gemm(const float* __restrict__ xs) {
    extern __shared__ __align__(16) __half sh[];
    const uint32_t smb = smem_u32(sh);
    const int tid = threadIdx.x, wid = tid >> 5, lane = tid & 31;
    const int n0 = blockIdx.x * 64, b = blockIdx.y;

    // cp.async entire W hi/lo [256 m][128 k] -> smem stride 136
    {
        #pragma unroll
        for (int v = 0; v < 16; v++) {
            int idx = tid + v * 256;         // 0..4095: m = idx>>4, k16 = idx&15
            int m = idx >> 4, k8 = idx & 15;
            cp16(smb + (uint32_t)(WHI_H + m * 136 + k8 * 8) * 2,
                 g_whi + (size_t)m * CIN + k8 * 8);
            cp16(smb + (uint32_t)(WLO_H + m * 136 + k8 * 8) * 2,
                 g_wlo + (size_t)m * CIN + k8 * 8);
        }
        CP_COMMIT;
    }
    // stage xs tile [64 rows][128 k] hi/lo (convert in regs)
    #pragma unroll
    for (int v = 0; v < 8; v++) {
        int id = tid + v * 256;
        int r = id >> 5, q = id & 31;
        float4 x = *(const float4*)(xs + ((size_t)(b * NN + n0 + r)) * CIN + q * 4);
        const float* xe = (const float*)&x;
        __half hv[4], lv[4];
        #pragma unroll
        for (int e = 0; e < 4; e++) {
            hv[e] = __float2half_rn(xe[e]);
            lv[e] = __float2half_rn(xe[e] - __half2float(hv[e]));
        }
        __half2 h01 = __halves2half2(hv[0], hv[1]), h23 = __halves2half2(hv[2], hv[3]);
        __half2 l01 = __halves2half2(lv[0], lv[1]), l23 = __halves2half2(lv[2], lv[3]);
        uint2 wh = {*(uint32_t*)&h01, *(uint32_t*)&h23};
        uint2 wl = {*(uint32_t*)&l01, *(uint32_t*)&l23};
        *(uint2*)(sh + XHI_H + r * 136 + q * 4) = wh;
        *(uint2*)(sh + XLO_H + r * 136 + q * 4) = wl;
    }
    CP_WAIT0;
    __syncthreads();

    float acc[2][8][4];
    #pragma unroll
    for (int mt = 0; mt < 2; mt++)
        #pragma unroll
        for (int nc = 0; nc < 8; nc++)
            #pragma unroll
            for (int e = 0; e < 4; e++) acc[mt][nc][e] = 0.f;

    const int arow = (lane & 7) + ((lane >> 3) & 1) * 8;
    const int acol = lane >> 4;
    const int brow = (lane & 7) + (lane >> 4) * 8;
    const int bkh  = (lane >> 3) & 1;

    #pragma unroll
    for (int ks = 0; ks < 8; ks++) {
        const int k0 = ks * 16;
        uint32_t awhi[2][4], awlo[2][4];
        #pragma unroll
        for (int mt = 0; mt < 2; mt++) {
            uint32_t aadr = smb + (uint32_t)(WHI_H + (wid * 32 + mt * 16 + arow) * 136
                                             + k0 + acol * 8) * 2;
            ldsm_x4(awhi[mt], aadr);
            ldsm_x4(awlo[mt], aadr + (uint32_t)(WLO_H - WHI_H) * 2);
        }
        #pragma unroll
        for (int nt = 0; nt < 4; nt++) {
            uint32_t badr = smb + (uint32_t)(XHI_H + (nt * 16 + brow) * 136
                                             + k0 + bkh * 8) * 2;
            uint32_t bhi[4], blo[4];
            ldsm_x4(bhi, badr);
            ldsm_x4(blo, badr + (uint32_t)XLO_H * 2);
            #pragma unroll
            for (int mt = 0; mt < 2; mt++) {
                mma_f16(acc[mt][2 * nt],     awhi[mt], bhi);
                mma_f16(acc[mt][2 * nt],     awhi[mt], blo);
                mma_f16(acc[mt][2 * nt],     awlo[mt], bhi);
                mma_f16(acc[mt][2 * nt + 1], awhi[mt], bhi + 2);
                mma_f16(acc[mt][2 * nt + 1], awhi[mt], blo + 2);
                mma_f16(acc[mt][2 * nt + 1], awlo[mt], bhi + 2);
            }
        }
    }

    // epilogue: g_hs_h[bh][d][n] fp16 (rows m = head*64+d, cols n)
    const int gid = lane >> 2, tg = lane & 3;
    #pragma unroll
    for (int mt = 0; mt < 2; mt++) {
        int m = wid * 32 + mt * 16 + gid;
        int head = m >> 6, dd = m & 63;
        __half* hb0 = g_hs_h + ((size_t)((b * H + head) * COUT + dd)) * NN + n0;
        __half* hb1 = g_hs_h + ((size_t)((b * H + head) * COUT + dd + 8)) * NN + n0;
        #pragma unroll
        for (int nc = 0; nc < 8; nc++) {
            int col = nc * 8 + 2 * tg;
            __half2 v0 = __floats2half2_rn(acc[mt][nc][0], acc[mt][nc][1]);
            __half2 v1 = __floats2half2_rn(acc[mt][nc][2], acc[mt][nc][3]);
            *(__half2*)(hb0 + col) = v0;
            *(__half2*)(hb1 + col) = v1;
        }
    }
}

// ---------------- K2 builder iteration (R12) ----------------
__device__ __forceinline__ void builder_iter(
    float* sm, __half* smh, uint32_t smb, const float* __restrict__ adjs,
    int b, int i0, int half_, int bt, int c4, int rb,
    int h, int jt, float Eh,
    const float* rel, const float* rA, const float* rC,
    float4* cur, float4* nxt)
{
    const int g = h * NJT + jt, buf = g & 1;
    const int bh = b * H + h;
    const int jbase = half_ * JH + jt * TJ;
    {
        const int jn = half_ * JH + ((jt + 1) & 15) * TJ;
        const float* apn = adjs + ((size_t)(b * NN + i0 + rb)) * NN + jn + c4 * 4;
        #pragma unroll
        for (int v = 0; v < 8; v++) nxt[v] = *(const float4*)(apn + (size_t)(v * 8) * NN);
    }
    if (g >= 2) BARS(3 + buf, 256);
    if (bt < 64) {
        float er = g_er[(size_t)bh * NN + jbase + bt];
        float u = er - Eh;
        sm[OFF_ER_F + buf * 192 + bt] = er;
        sm[OFF_ER_F + buf * 192 + 64 + bt] = ex2f(u);
        sm[OFF_ER_F + buf * 192 + 128 + bt] = ex2f(0.1f * u);
    }
    {
        uint32_t hB = smb + OFF_HS_BYTES + buf * HSBUF_BYTES;
        const __half* hsrc = g_hs_h + (size_t)bh * COUT * NN + jbase;
        #pragma unroll
        for (int v = 0; v < 4; v++) {
            int idx = bt + v * 128;
            int d = idx >> 3, j8 = idx & 7;
            cp16(hB + (uint32_t)(d * PSTR + j8 * 8) * 2, hsrc + (size_t)d * NN + j8 * 8);
        }
        CP_COMMIT;
    }
    BARS(5, 128);
    {
        float4 er4 = *(const float4*)(sm + OFF_ER_F + buf * 192 + c4 * 4);
        float4 B4  = *(const float4*)(sm + OFF_ER_F + buf * 192 + 64 + c4 * 4);
        float4 D4  = *(const float4*)(sm + OFF_ER_F + buf * 192 + 128 + c4 * 4);
        const float* erv = (const float*)&er4;
        const float* Bv  = (const float*)&B4;
        const float* Dv  = (const float*)&D4;
        __half* sPb = smh + (buf * PBUF_BYTES) / 2;
        #pragma unroll
        for (int v = 0; v < 8; v++) {
            int r = rb + v * 8;
            const float* av = (const float*)&cur[v];
            float p[4];
            #pragma unroll
            for (int e = 0; e < 4; e++) {
                float s = rel[v] + erv[e];
                float f1 = (s > 0.f) ? rA[v] : rC[v];
                float f2 = (s > 0.f) ? Bv[e] : Dv[e];
                p[e] = av[e] * f1 * f2;
            }
            __half2 p01 = __floats2half2_rn(p[0], p[1]);
            __half2 p23 = __floats2half2_rn(p[2], p[3]);
            uint2 w = {*(uint32_t*)&p01, *(uint32_t*)&p23};
            *(uint2*)(sPb + r * PSTR + c4 * 4) = w;
        }
    }
    CP_WAIT0;
    BARA(1 + buf, 256);
}

// ---------------- K2: warp-specialized fp16 mma flash loop (R12) ----------------
__global__ __launch_bounds__(256, 2) void k2_attn(const float* __restrict__ adjs) {
    extern __shared__ float sm[];
    __half* smh = (__half*)sm;
    const uint32_t smb = smem_u32(sm);
    const int tid = threadIdx.x, wid = tid >> 5, lane = tid & 31;
    const int i0 = blockIdx.x * TI, half_ = blockIdx.y, b = blockIdx.z;

    for (int idx = tid; idx < 2 * 8 * PSTR; idx += 256) {
        int buf = idx / (8 * PSTR);
        int rem = idx % (8 * PSTR);
        int r8 = rem / PSTR, c = rem % PSTR;
        smh[(OFF_HS_BYTES + buf * HSBUF_BYTES) / 2 + (64 + r8) * PSTR + c] =
            (r8 == 0 && c < 64) ? __float2half(1.f) : __float2half(0.f);
    }
    if (tid < 256) {
        int h = tid >> 6, r = tid & 63;
        int bh = b * H + h;
        float e = g_el[(size_t)bh * NN + i0 + r];
        float E = fdec(g_emax_key[bh]);
        float t = e + E;
        float m = fmaxf(t, 0.1f * t);
        sm[OFF_EL_F + h * 192 + r] = e;
        sm[OFF_EL_F + h * 192 + 64 + r] = ex2f(t - m);
        sm[OFF_EL_F + h * 192 + 128 + r] = ex2f(0.1f * t - m);
    }
    __syncthreads();

    if (wid >= 4) {
        const int bt = tid & 127;
        const int c4 = bt & 15, rb = bt >> 4;
        float4 ajA[8], ajB[8];
        {
            const float* ap0 = adjs + ((size_t)(b * NN + i0 + rb)) * NN + half_ * JH + c4 * 4;
            #pragma unroll
            for (int v = 0; v < 8; v++) ajA[v] = *(const float4*)(ap0 + (size_t)(v * 8) * NN);
        }
        for (int h = 0; h < H; h++) {
            const float Eh = fdec(g_emax_key[b * H + h]);
            float rel[8], rA[8], rC[8];
            #pragma unroll
            for (int v = 0; v < 8; v++) {
                int r = rb + v * 8;
                rel[v] = sm[OFF_EL_F + h * 192 + r];
                rA[v]  = sm[OFF_EL_F + h * 192 + 64 + r];
                rC[v]  = sm[OFF_EL_F + h * 192 + 128 + r];
            }
            #pragma unroll 1
            for (int jp = 0; jp < 8; jp++) {
                builder_iter(sm, smh, smb, adjs, b, i0, half_, bt, c4, rb,
                             h, 2 * jp, Eh, rel, rA, rC, ajA, ajB);
                builder_iter(sm, smh, smb, adjs, b, i0, half_, bt, c4, rb,
                             h, 2 * jp + 1, Eh, rel, rA, rC, ajB, ajA);
            }
        }
    } else {
        const int gid = lane >> 2, tg = lane & 3;
        const uint32_t aRow = (uint32_t)(wid * 16 + (lane & 7) + ((lane >> 3) & 1) * 8);
        const uint32_t aOff = (aRow * PSTR + (lane >> 4) * 8) * 2;
        const uint32_t bRowL = (uint32_t)((lane & 7) + (lane >> 4) * 8);
        const uint32_t bOff = (bRowL * PSTR + ((lane >> 3) & 1) * 8) * 2;
        const int ol = lane & 15;
        const uint32_t oOff = (uint32_t)(((64 + (ol & 7)) * PSTR + ((ol >> 3) & 1) * 8) * 2);
        for (int h = 0; h < H; h++) {
            const int bh = b * H + h;
            float acc[9][4];
            #pragma unroll
            for (int nc = 0; nc < 9; nc++)
                #pragma unroll
                for (int e = 0; e < 4; e++) acc[nc][e] = 0.f;
            for (int jt = 0; jt < NJT; jt++) {
                const int g = h * NJT + jt, buf = g & 1;
                BARS(1 + buf, 256);
                uint32_t pA = smb + buf * PBUF_BYTES + aOff;
                uint32_t hB = smb + OFF_HS_BYTES + buf * HSBUF_BYTES;
                #pragma unroll
                for (int ks = 0; ks < 4; ks++) {
                    uint32_t a[4];
                    ldsm_x4(a, pA); pA += 32;
                    #pragma unroll
                    for (int p2 = 0; p2 < 4; p2++) {
                        uint32_t bb[4];
                        ldsm_x4(bb, hB + bOff + (uint32_t)p2 * (16 * PSTR * 2) + ks * 32);
                        mma_f16(acc[2 * p2], a, bb);
                        mma_f16(acc[2 * p2 + 1], a, bb + 2);
                    }
                    uint32_t oo[2];
                    ldsm_x2(oo, hB + oOff + ks * 32);
                    mma_f16(acc[8], a, oo);
                }
                BARA(3 + buf, 256);
            }
            const int r0 = i0 + wid * 16 + gid;
            float* ob = g_opart[half_] + ((size_t)b * NN) * HD;
            #pragma unroll
            for (int nc = 0; nc < 8; nc++) {
                int col = h * 64 + nc * 8 + 2 * tg;
                float2 v0 = {acc[nc][0], acc[nc][1]};
                float2 v1 = {acc[nc][2], acc[nc][3]};
                *(float2*)(ob + (size_t)r0 * HD + col) = v0;
                *(float2*)(ob + (size_t)(r0 + 8) * HD + col) = v1;
            }
            if (tg == 0) {
                g_lpart[half_][(size_t)bh * NN + r0] = acc[8][0];
                g_lpart[half_][(size_t)bh * NN + r0 + 8] = acc[8][2];
            }
        }
    }
}

// ---------------- K3: combine halves + normalize (8 floats/thread) ----------------
__global__ __launch_bounds__(256) void k3_combine(float* __restrict__ out) {
    int idx = blockIdx.x * 256 + threadIdx.x;
    size_t flat = (size_t)idx * 8;
    int b   = (int)(flat >> 19);
    int rem = (int)(flat & 524287);
    int i = rem >> 8;
    int h = (rem >> 6) & 3;
    size_t li = (size_t)(b * H + h) * NN + i;
    float l = g_lpart[0][li] + g_lpart[1][li];
    float inv = (l > 0.f) ? (1.f / l) : 0.f;
    float4 a0 = *(const float4*)(g_opart[0] + flat);
    float4 a1 = *(const float4*)(g_opart[0] + flat + 4);
    float4 b0 = *(const float4*)(g_opart[1] + flat);
    float4 b1 = *(const float4*)(g_opart[1] + flat + 4);
    float4 w0 = {(a0.x + b0.x) * inv, (a0.y + b0.y) * inv,
                 (a0.z + b0.z) * inv, (a0.w + b0.w) * inv};
    float4 w1 = {(a1.x + b1.x) * inv, (a1.y + b1.y) * inv,
                 (a1.z + b1.z) * inv, (a1.w + b1.w) * inv};
    *(float4*)(out + flat) = w0;
    *(float4*)(out + flat + 4) = w1;
}

extern "C" void kernel_launch(void* const* d_in, const int* in_sizes, int n_in,
                              void* d_out, int out_size) {
    const float* xs   = (const float*)d_in[0];
    const float* adjs = (const float*)d_in[1];
    const float* W1   = (const float*)d_in[2];
    const float* a_l  = (const float*)d_in[3];
    const float* a_r  = (const float*)d_in[4];
    float* out = (float*)d_out;

    cudaFuncSetAttribute(k1h_gemm, cudaFuncAttributeMaxDynamicSharedMemorySize, SMEM_K1H);
    cudaFuncSetAttribute(k2_attn, cudaFuncAttributeMaxDynamicSharedMemorySize, SMEM_K2);

    k0w<<<34, 256>>>(W1, a_l, a_r);
    k0b_elr<<<32, 256>>>(xs);
    k1h_gemm<<<dim3(32, 4), 256, SMEM_K1H>>>(xs);
    k2_attn<<<dim3(32, 2, 4), 256, SMEM_K2>>>(adjs);
    k3_combine<<<(BS * NN * HD / 8) / 256, 256>>>(out);
}

// round 14
// speedup vs baseline: 1.1238x; 1.1238x over previous
#include <cuda_runtime.h>
#include <cuda_fp16.h>
#include <cstdint>

#define BS   4
#define NN   2048
#define CIN  128
#define COUT 64
#define H    4
#define HD   256
#define TI   64
#define TJ   64
#define JH   1024
#define NJT  16
#define LOG2E 1.4426950408889634f

// device scratch (allocation-free)
__device__ __half g_hs_h[(size_t)BS * H * COUT * NN];  // [bh][d][n] fp16 (transposed)
__device__ float g_el[BS * H * NN];                    // pre-scaled by log2e
__device__ float g_er[BS * H * NN];                    // pre-scaled by log2e
__device__ unsigned int g_emax_key[BS * H];            // float-ordered key (0-init; idempotent)
__device__ float g_opart[2][(size_t)BS * NN * HD];
__device__ float g_lpart[2][BS * H * NN];

// K2 smem layout (R7/R12)
#define PSTR 72
#define PBUF_BYTES  9216
#define HSBUF_BYTES 10368
#define OFF_HS_BYTES 18432
#define OFF_ER_F 9792          // per buf {er[64],B[64],D[64]} x2
#define OFF_EL_F 10176         // per head {el[64],A[64],C[64]} x4
#define SMEM_K2 44032

__device__ __forceinline__ uint32_t smem_u32(const void* p) {
    uint32_t a;
    asm("{ .reg .u64 t; cvta.to.shared.u64 t, %1; cvt.u32.u64 %0, t; }" : "=r"(a) : "l"(p));
    return a;
}
__device__ __forceinline__ float ex2f(float x) {
    float r;
    asm("ex2.approx.f32 %0, %1;" : "=f"(r) : "f"(x));
    return r;
}
__device__ __forceinline__ unsigned int fenc(float f) {
    unsigned int b = __float_as_uint(f);
    return (b & 0x80000000u) ? ~b : (b | 0x80000000u);
}
__device__ __forceinline__ float fdec(unsigned int k) {
    unsigned int b = (k & 0x80000000u) ? (k ^ 0x80000000u) : ~k;
    return __uint_as_float(b);
}
__device__ __forceinline__ void mma_f16(float* d, const uint32_t* a, const uint32_t* b) {
    asm volatile(
        "mma.sync.aligned.m16n8k16.row.col.f32.f16.f16.f32 "
        "{%0,%1,%2,%3}, {%4,%5,%6,%7}, {%8,%9}, {%0,%1,%2,%3};"
        : "+f"(d[0]), "+f"(d[1]), "+f"(d[2]), "+f"(d[3])
        : "r"(a[0]), "r"(a[1]), "r"(a[2]), "r"(a[3]), "r"(b[0]), "r"(b[1]));
}
__device__ __forceinline__ void ldsm_x4(uint32_t* r, uint32_t addr) {
    asm volatile("ldmatrix.sync.aligned.m8n8.x4.shared.b16 {%0,%1,%2,%3}, [%4];"
                 : "=r"(r[0]), "=r"(r[1]), "=r"(r[2]), "=r"(r[3]) : "r"(addr));
}
__device__ __forceinline__ void ldsm_x2(uint32_t* r, uint32_t addr) {
    asm volatile("ldmatrix.sync.aligned.m8n8.x2.shared.b16 {%0,%1}, [%2];"
                 : "=r"(r[0]), "=r"(r[1]) : "r"(addr));
}
__device__ __forceinline__ void cp16(uint32_t dst, const void* src) {
    asm volatile("cp.async.ca.shared.global [%0], [%1], 16;" :: "r"(dst), "l"(src));
}
#define CP_COMMIT asm volatile("cp.async.commit_group;" ::: "memory")
#define CP_WAIT0  asm volatile("cp.async.wait_group 0;" ::: "memory")
#define BARS(id, n) asm volatile("bar.sync %0, %1;" :: "r"(id), "r"(n) : "memory")
#define BARA(id, n) asm volatile("bar.arrive %0, %1;" :: "r"(id), "r"(n) : "memory")

// ---------------- K1: hs = xs @ W1 (ALL 4 heads per CTA), fp16-T store, el/er, emax ----------------
__global__ __launch_bounds__(256) void k1_gemm(const float* __restrict__ xs,
                                               const float* __restrict__ W1,
                                               const float* __restrict__ a_l,
                                               const float* __restrict__ a_r) {
    const int bx = blockIdx.x, b = blockIdx.y;
    const int tid = threadIdx.x;
    const int ig = tid >> 4, cg = tid & 15;
    const int r0 = ig * 4;
    const int hd = cg >> 2;            // my head
    const int lc0 = (cg & 3) * 16;     // local col base within head (16 cols)

    __shared__ float As[32][68];
    __shared__ float Bs[32][4 * 68];   // [k][head*68 + localcol]
    __shared__ float sred[16][64];
    __shared__ float smax[H][2];

    float acc[4][16] = {};
    const float* xbase = xs + ((size_t)(b * NN + bx * 64)) * CIN;

    for (int kc = 0; kc < CIN; kc += 32) {
        // As: 64 rows x 32 k, transposed
        int lin = tid;
        #pragma unroll
        for (int t = 0; t < 2; t++, lin += 256) {
            int r = lin >> 3, k4 = lin & 7;
            float4 v = *(const float4*)(xbase + r * CIN + kc + k4 * 4);
            As[k4 * 4 + 0][r] = v.x; As[k4 * 4 + 1][r] = v.y;
            As[k4 * 4 + 2][r] = v.z; As[k4 * 4 + 3][r] = v.w;
        }
        // Bs: 32 k x 256 cols (all heads), head-blocked stride 68
        lin = tid;
        #pragma unroll
        for (int t = 0; t < 8; t++, lin += 256) {
            int k = lin >> 6, c4 = lin & 63;
            float4 v = *(const float4*)(W1 + (size_t)(kc + k) * HD + c4 * 4);
            *(float4*)&Bs[k][(c4 >> 4) * 68 + (c4 & 15) * 4] = v;
        }
        __syncthreads();
        #pragma unroll
        for (int k = 0; k < 32; k++) {
            float4 aq = *(const float4*)&As[k][r0];
            float ar[4] = {aq.x, aq.y, aq.z, aq.w};
            float br[16];
            #pragma unroll
            for (int q = 0; q < 4; q++)
                *(float4*)&br[q * 4] = *(const float4*)&Bs[k][hd * 68 + lc0 + q * 4];
            #pragma unroll
            for (int r = 0; r < 4; r++)
                #pragma unroll
                for (int c = 0; c < 16; c++) acc[r][c] += ar[r] * br[c];
        }
        __syncthreads();
    }

    const int bh = b * H + hd;
    // transposed fp16 store: g_hs_h[bh][d][n], d = lc0 + c
    #pragma unroll
    for (int c = 0; c < 16; c++) {
        __half2 lo = __floats2half2_rn(acc[0][c], acc[1][c]);
        __half2 hi = __floats2half2_rn(acc[2][c], acc[3][c]);
        uint2 w = {*(uint32_t*)&lo, *(uint32_t*)&hi};
        *(uint2*)(g_hs_h + ((size_t)(bh * COUT + lc0 + c)) * NN + bx * 64 + r0) = w;
    }
    // el/er partials over my 16 cols (a vectors indexed by local d)
    float pl[4] = {}, pr[4] = {};
    #pragma unroll
    for (int r = 0; r < 4; r++)
        #pragma unroll
        for (int c = 0; c < 16; c++) {
            pl[r] += acc[r][c] * __ldg(a_l + lc0 + c);
            pr[r] += acc[r][c] * __ldg(a_r + lc0 + c);
        }
    #pragma unroll
    for (int r = 0; r < 4; r++) sred[cg][r0 + r] = pl[r];
    __syncthreads();
    if (tid < 64) {
        #pragma unroll
        for (int h = 0; h < H; h++) {
            float s = sred[h * 4][tid] + sred[h * 4 + 1][tid]
                    + sred[h * 4 + 2][tid] + sred[h * 4 + 3][tid];
            g_el[(size_t)(b * H + h) * NN + bx * 64 + tid] = s * LOG2E;
        }
    }
    __syncthreads();
    #pragma unroll
    for (int r = 0; r < 4; r++) sred[cg][r0 + r] = pr[r];
    __syncthreads();
    if (tid < 64) {
        #pragma unroll
        for (int h = 0; h < H; h++) {
            float s = sred[h * 4][tid] + sred[h * 4 + 1][tid]
                    + sred[h * 4 + 2][tid] + sred[h * 4 + 3][tid];
            float es = s * LOG2E;
            g_er[(size_t)(b * H + h) * NN + bx * 64 + tid] = es;
            float m = es;
            #pragma unroll
            for (int o = 16; o > 0; o >>= 1)
                m = fmaxf(m, __shfl_xor_sync(0xffffffffu, m, o));
            if ((tid & 31) == 0) smax[h][tid >> 5] = m;
        }
    }
    __syncthreads();
    if (tid < H)
        atomicMax(&g_emax_key[b * H + tid], fenc(fmaxf(smax[tid][0], smax[tid][1])));
}

// ---------------- K2 builder iteration (R12, unchanged) ----------------
__device__ __forceinline__ void builder_iter(
    float* sm, __half* smh, uint32_t smb, const float* __restrict__ adjs,
    int b, int i0, int half_, int bt, int c4, int rb,
    int h, int jt, float Eh,
    const float* rel, const float* rA, const float* rC,
    float4* cur, float4* nxt)
{
    const int g = h * NJT + jt, buf = g & 1;
    const int bh = b * H + h;
    const int jbase = half_ * JH + jt * TJ;
    {
        const int jn = half_ * JH + ((jt + 1) & 15) * TJ;
        const float* apn = adjs + ((size_t)(b * NN + i0 + rb)) * NN + jn + c4 * 4;
        #pragma unroll
        for (int v = 0; v < 8; v++) nxt[v] = *(const float4*)(apn + (size_t)(v * 8) * NN);
    }
    if (g >= 2) BARS(3 + buf, 256);
    if (bt < 64) {
        float er = g_er[(size_t)bh * NN + jbase + bt];
        float u = er - Eh;
        sm[OFF_ER_F + buf * 192 + bt] = er;
        sm[OFF_ER_F + buf * 192 + 64 + bt] = ex2f(u);
        sm[OFF_ER_F + buf * 192 + 128 + bt] = ex2f(0.1f * u);
    }
    {
        uint32_t hB = smb + OFF_HS_BYTES + buf * HSBUF_BYTES;
        const __half* hsrc = g_hs_h + (size_t)bh * COUT * NN + jbase;
        #pragma unroll
        for (int v = 0; v < 4; v++) {
            int idx = bt + v * 128;
            int d = idx >> 3, j8 = idx & 7;
            cp16(hB + (uint32_t)(d * PSTR + j8 * 8) * 2, hsrc + (size_t)d * NN + j8 * 8);
        }
        CP_COMMIT;
    }
    BARS(5, 128);
    {
        float4 er4 = *(const float4*)(sm + OFF_ER_F + buf * 192 + c4 * 4);
        float4 B4  = *(const float4*)(sm + OFF_ER_F + buf * 192 + 64 + c4 * 4);
        float4 D4  = *(const float4*)(sm + OFF_ER_F + buf * 192 + 128 + c4 * 4);
        const float* erv = (const float*)&er4;
        const float* Bv  = (const float*)&B4;
        const float* Dv  = (const float*)&D4;
        __half* sPb = smh + (buf * PBUF_BYTES) / 2;
        #pragma unroll
        for (int v = 0; v < 8; v++) {
            int r = rb + v * 8;
            const float* av = (const float*)&cur[v];
            float p[4];
            #pragma unroll
            for (int e = 0; e < 4; e++) {
                float s = rel[v] + erv[e];
                float f1 = (s > 0.f) ? rA[v] : rC[v];
                float f2 = (s > 0.f) ? Bv[e] : Dv[e];
                p[e] = av[e] * f1 * f2;
            }
            __half2 p01 = __floats2half2_rn(p[0], p[1]);
            __half2 p23 = __floats2half2_rn(p[2], p[3]);
            uint2 w = {*(uint32_t*)&p01, *(uint32_t*)&p23};
            *(uint2*)(sPb + r * PSTR + c4 * 4) = w;
        }
    }
    CP_WAIT0;
    BARA(1 + buf, 256);
}

// ---------------- K2: warp-specialized fp16 mma flash loop (R12, unchanged) ----------------
__global__ __launch_bounds__(256, 2) void k2_attn(const float* __restrict__ adjs) {
    extern __shared__ float sm[];
    __half* smh = (__half*)sm;
    const uint32_t smb = smem_u32(sm);
    const int tid = threadIdx.x, wid = tid >> 5, lane = tid & 31;
    const int i0 = blockIdx.x * TI, half_ = blockIdx.y, b = blockIdx.z;

    for (int idx = tid; idx < 2 * 8 * PSTR; idx += 256) {
        int buf = idx / (8 * PSTR);
        int rem = idx % (8 * PSTR);
        int r8 = rem / PSTR, c = rem % PSTR;
        smh[(OFF_HS_BYTES + buf * HSBUF_BYTES) / 2 + (64 + r8) * PSTR + c] =
            (r8 == 0 && c < 64) ? __float2half(1.f) : __float2half(0.f);
    }
    if (tid < 256) {
        int h = tid >> 6, r = tid & 63;
        int bh = b * H + h;
        float e = g_el[(size_t)bh * NN + i0 + r];
        float E = fdec(g_emax_key[bh]);
        float t = e + E;
        float m = fmaxf(t, 0.1f * t);
        sm[OFF_EL_F + h * 192 + r] = e;
        sm[OFF_EL_F + h * 192 + 64 + r] = ex2f(t - m);
        sm[OFF_EL_F + h * 192 + 128 + r] = ex2f(0.1f * t - m);
    }
    __syncthreads();

    if (wid >= 4) {
        const int bt = tid & 127;
        const int c4 = bt & 15, rb = bt >> 4;
        float4 ajA[8], ajB[8];
        {
            const float* ap0 = adjs + ((size_t)(b * NN + i0 + rb)) * NN + half_ * JH + c4 * 4;
            #pragma unroll
            for (int v = 0; v < 8; v++) ajA[v] = *(const float4*)(ap0 + (size_t)(v * 8) * NN);
        }
        for (int h = 0; h < H; h++) {
            const float Eh = fdec(g_emax_key[b * H + h]);
            float rel[8], rA[8], rC[8];
            #pragma unroll
            for (int v = 0; v < 8; v++) {
                int r = rb + v * 8;
                rel[v] = sm[OFF_EL_F + h * 192 + r];
                rA[v]  = sm[OFF_EL_F + h * 192 + 64 + r];
                rC[v]  = sm[OFF_EL_F + h * 192 + 128 + r];
            }
            #pragma unroll 1
            for (int jp = 0; jp < 8; jp++) {
                builder_iter(sm, smh, smb, adjs, b, i0, half_, bt, c4, rb,
                             h, 2 * jp, Eh, rel, rA, rC, ajA, ajB);
                builder_iter(sm, smh, smb, adjs, b, i0, half_, bt, c4, rb,
                             h, 2 * jp + 1, Eh, rel, rA, rC, ajB, ajA);
            }
        }
    } else {
        const int gid = lane >> 2, tg = lane & 3;
        const uint32_t aRow = (uint32_t)(wid * 16 + (lane & 7) + ((lane >> 3) & 1) * 8);
        const uint32_t aOff = (aRow * PSTR + (lane >> 4) * 8) * 2;
        const uint32_t bRowL = (uint32_t)((lane & 7) + (lane >> 4) * 8);
        const uint32_t bOff = (bRowL * PSTR + ((lane >> 3) & 1) * 8) * 2;
        const int ol = lane & 15;
        const uint32_t oOff = (uint32_t)(((64 + (ol & 7)) * PSTR + ((ol >> 3) & 1) * 8) * 2);
        for (int h = 0; h < H; h++) {
            const int bh = b * H + h;
            float acc[9][4];
            #pragma unroll
            for (int nc = 0; nc < 9; nc++)
                #pragma unroll
                for (int e = 0; e < 4; e++) acc[nc][e] = 0.f;
            for (int jt = 0; jt < NJT; jt++) {
                const int g = h * NJT + jt, buf = g & 1;
                BARS(1 + buf, 256);
                uint32_t pA = smb + buf * PBUF_BYTES + aOff;
                uint32_t hB = smb + OFF_HS_BYTES + buf * HSBUF_BYTES;
                #pragma unroll
                for (int ks = 0; ks < 4; ks++) {
                    uint32_t a[4];
                    ldsm_x4(a, pA); pA += 32;
                    #pragma unroll
                    for (int p2 = 0; p2 < 4; p2++) {
                        uint32_t bb[4];
                        ldsm_x4(bb, hB + bOff + (uint32_t)p2 * (16 * PSTR * 2) + ks * 32);
                        mma_f16(acc[2 * p2], a, bb);
                        mma_f16(acc[2 * p2 + 1], a, bb + 2);
                    }
                    uint32_t oo[2];
                    ldsm_x2(oo, hB + oOff + ks * 32);
                    mma_f16(acc[8], a, oo);
                }
                BARA(3 + buf, 256);
            }
            const int r0 = i0 + wid * 16 + gid;
            float* ob = g_opart[half_] + ((size_t)b * NN) * HD;
            #pragma unroll
            for (int nc = 0; nc < 8; nc++) {
                int col = h * 64 + nc * 8 + 2 * tg;
                float2 v0 = {acc[nc][0], acc[nc][1]};
                float2 v1 = {acc[nc][2], acc[nc][3]};
                *(float2*)(ob + (size_t)r0 * HD + col) = v0;
                *(float2*)(ob + (size_t)(r0 + 8) * HD + col) = v1;
            }
            if (tg == 0) {
                g_lpart[half_][(size_t)bh * NN + r0] = acc[8][0];
                g_lpart[half_][(size_t)bh * NN + r0 + 8] = acc[8][2];
            }
        }
    }
}

// ---------------- K3: combine halves + normalize (8 floats/thread, R12) ----------------
__global__ __launch_bounds__(256) void k3_combine(float* __restrict__ out) {
    int idx = blockIdx.x * 256 + threadIdx.x;
    size_t flat = (size_t)idx * 8;
    int b   = (int)(flat >> 19);
    int rem = (int)(flat & 524287);
    int i = rem >> 8;
    int h = (rem >> 6) & 3;
    size_t li = (size_t)(b * H + h) * NN + i;
    float l = g_lpart[0][li] + g_lpart[1][li];
    float inv = (l > 0.f) ? (1.f / l) : 0.f;
    float4 a0 = *(const float4*)(g_opart[0] + flat);
    float4 a1 = *(const float4*)(g_opart[0] + flat + 4);
    float4 b0 = *(const float4*)(g_opart[1] + flat);
    float4 b1 = *(const float4*)(g_opart[1] + flat + 4);
    float4 w0 = {(a0.x + b0.x) * inv, (a0.y + b0.y) * inv,
                 (a0.z + b0.z) * inv, (a0.w + b0.w) * inv};
    float4 w1 = {(a1.x + b1.x) * inv, (a1.y + b1.y) * inv,
                 (a1.z + b1.z) * inv, (a1.w + b1.w) * inv};
    *(float4*)(out + flat) = w0;
    *(float4*)(out + flat + 4) = w1;
}

extern "C" void kernel_launch(void* const* d_in, const int* in_sizes, int n_in,
                              void* d_out, int out_size) {
    const float* xs   = (const float*)d_in[0];
    const float* adjs = (const float*)d_in[1];
    const float* W1   = (const float*)d_in[2];
    const float* a_l  = (const float*)d_in[3];
    const float* a_r  = (const float*)d_in[4];
    float* out = (float*)d_out;

    cudaFuncSetAttribute(k2_attn, cudaFuncAttributeMaxDynamicSharedMemorySize, SMEM_K2);

    k1_gemm<<<dim3(32, 4), 256>>>(xs, W1, a_l, a_r);
    k2_attn<<<dim3(32, 2, 4), 256, SMEM_K2>>>(adjs);
    k3_combine<<<(BS * NN * HD / 8) / 256, 256>>>(out);
}

// round 15
// speedup vs baseline: 1.2054x; 1.0726x over previous
#include <cuda_runtime.h>
#include <cuda_fp16.h>
#include <cstdint>

#define BS   4
#define NN   2048
#define CIN  128
#define COUT 64
#define H    4
#define HD   256
#define TI   64
#define TJ   64
#define JH   1024
#define NJT  16
#define LOG2E 1.4426950408889634f

// device scratch (allocation-free)
__device__ __half g_hs_h[(size_t)BS * H * COUT * NN];  // [bh][d][n] fp16 (transposed)
__device__ float g_el[BS * H * NN];                    // pre-scaled by log2e
__device__ float g_er[BS * H * NN];                    // pre-scaled by log2e
__device__ unsigned int g_emax_key[BS * H];            // float-ordered key (0-init; idempotent)
__device__ float g_opart[2][(size_t)BS * NN * HD];
__device__ float g_lpart[2][BS * H * NN];

// K2 smem layout (R7/R12)
#define PSTR 72
#define PBUF_BYTES  9216
#define HSBUF_BYTES 10368
#define OFF_HS_BYTES 18432
#define OFF_ER_F 9792          // per buf {er[64],B[64],D[64]} x2
#define OFF_EL_F 10176         // per head {el[64],A[64],C[64]} x4
#define SMEM_K2 44032

__device__ __forceinline__ uint32_t smem_u32(const void* p) {
    uint32_t a;
    asm("{ .reg .u64 t; cvta.to.shared.u64 t, %1; cvt.u32.u64 %0, t; }" : "=r"(a) : "l"(p));
    return a;
}
__device__ __forceinline__ float ex2f(float x) {
    float r;
    asm("ex2.approx.f32 %0, %1;" : "=f"(r) : "f"(x));
    return r;
}
__device__ __forceinline__ unsigned int fenc(float f) {
    unsigned int b = __float_as_uint(f);
    return (b & 0x80000000u) ? ~b : (b | 0x80000000u);
}
__device__ __forceinline__ float fdec(unsigned int k) {
    unsigned int b = (k & 0x80000000u) ? (k ^ 0x80000000u) : ~k;
    return __uint_as_float(b);
}
__device__ __forceinline__ void mma_f16(float* d, const uint32_t* a, const uint32_t* b) {
    asm volatile(
        "mma.sync.aligned.m16n8k16.row.col.f32.f16.f16.f32 "
        "{%0,%1,%2,%3}, {%4,%5,%6,%7}, {%8,%9}, {%0,%1,%2,%3};"
        : "+f"(d[0]), "+f"(d[1]), "+f"(d[2]), "+f"(d[3])
        : "r"(a[0]), "r"(a[1]), "r"(a[2]), "r"(a[3]), "r"(b[0]), "r"(b[1]));
}
__device__ __forceinline__ void ldsm_x4(uint32_t* r, uint32_t addr) {
    asm volatile("ldmatrix.sync.aligned.m8n8.x4.shared.b16 {%0,%1,%2,%3}, [%4];"
                 : "=r"(r[0]), "=r"(r[1]), "=r"(r[2]), "=r"(r[3]) : "r"(addr));
}
__device__ __forceinline__ void ldsm_x2(uint32_t* r, uint32_t addr) {
    asm volatile("ldmatrix.sync.aligned.m8n8.x2.shared.b16 {%0,%1}, [%2];"
                 : "=r"(r[0]), "=r"(r[1]) : "r"(addr));
}
__device__ __forceinline__ void cp16(uint32_t dst, const void* src) {
    asm volatile("cp.async.ca.shared.global [%0], [%1], 16;" :: "r"(dst), "l"(src));
}
#define CP_COMMIT asm volatile("cp.async.commit_group;" ::: "memory")
#define CP_WAIT0  asm volatile("cp.async.wait_group 0;" ::: "memory")
#define BARS(id, n) asm volatile("bar.sync %0, %1;" :: "r"(id), "r"(n) : "memory")
#define BARA(id, n) asm volatile("bar.arrive %0, %1;" :: "r"(id), "r"(n) : "memory")

// ---------------- K1: hs = xs @ W1 (per-head), fp16-T store, el/er, fused emax (R12) ----------------
__global__ __launch_bounds__(256) void k1_gemm(const float* __restrict__ xs,
                                               const float* __restrict__ W1,
                                               const float* __restrict__ a_l,
                                               const float* __restrict__ a_r) {
    const int bx = blockIdx.x, head = blockIdx.y, b = blockIdx.z;
    const int tid = threadIdx.x;
    const int ig = tid >> 4, cg = tid & 15;
    const int r0 = ig * 4, c0 = cg * 4;

    __shared__ float As[32][68];
    __shared__ float Bs[32][68];
    __shared__ float sred[16][64];
    __shared__ float smax[2];

    float acc[4][4] = {};
    const float* xbase = xs + ((size_t)(b * NN + bx * 64)) * CIN;
    const float* wbase = W1 + head * COUT;

    for (int kc = 0; kc < CIN; kc += 32) {
        int lin = tid;
        #pragma unroll
        for (int t = 0; t < 2; t++, lin += 256) {
            int r = lin >> 3, k4 = lin & 7;
            float4 v = *(const float4*)(xbase + r * CIN + kc + k4 * 4);
            As[k4 * 4 + 0][r] = v.x; As[k4 * 4 + 1][r] = v.y;
            As[k4 * 4 + 2][r] = v.z; As[k4 * 4 + 3][r] = v.w;
        }
        lin = tid;
        #pragma unroll
        for (int t = 0; t < 2; t++, lin += 256) {
            int k = lin >> 4, c4 = lin & 15;
            float4 v = *(const float4*)(wbase + (size_t)(kc + k) * HD + c4 * 4);
            *(float4*)&Bs[k][c4 * 4] = v;
        }
        __syncthreads();
        #pragma unroll
        for (int k = 0; k < 32; k++) {
            float4 aq = *(const float4*)&As[k][r0];
            float4 bq = *(const float4*)&Bs[k][c0];
            float ar[4] = {aq.x, aq.y, aq.z, aq.w};
            float br[4] = {bq.x, bq.y, bq.z, bq.w};
            #pragma unroll
            for (int r = 0; r < 4; r++)
                #pragma unroll
                for (int c = 0; c < 4; c++) acc[r][c] += ar[r] * br[c];
        }
        __syncthreads();
    }

    const int bh = b * H + head;
    #pragma unroll
    for (int c = 0; c < 4; c++) {
        __half2 lo = __floats2half2_rn(acc[0][c], acc[1][c]);
        __half2 hi = __floats2half2_rn(acc[2][c], acc[3][c]);
        uint2 w = {*(uint32_t*)&lo, *(uint32_t*)&hi};
        *(uint2*)(g_hs_h + ((size_t)(bh * COUT + c0 + c)) * NN + bx * 64 + r0) = w;
    }
    float pl[4] = {}, pr[4] = {};
    #pragma unroll
    for (int r = 0; r < 4; r++)
        #pragma unroll
        for (int c = 0; c < 4; c++) {
            pl[r] += acc[r][c] * __ldg(a_l + c0 + c);
            pr[r] += acc[r][c] * __ldg(a_r + c0 + c);
        }
    #pragma unroll
    for (int r = 0; r < 4; r++) sred[cg][r0 + r] = pl[r];
    __syncthreads();
    if (tid < 64) {
        float s = 0.f;
        #pragma unroll
        for (int g = 0; g < 16; g++) s += sred[g][tid];
        g_el[(size_t)bh * NN + bx * 64 + tid] = s * LOG2E;
    }
    __syncthreads();
    #pragma unroll
    for (int r = 0; r < 4; r++) sred[cg][r0 + r] = pr[r];
    __syncthreads();
    if (tid < 64) {
        float s = 0.f;
        #pragma unroll
        for (int g = 0; g < 16; g++) s += sred[g][tid];
        float es = s * LOG2E;
        g_er[(size_t)bh * NN + bx * 64 + tid] = es;
        float m = es;
        #pragma unroll
        for (int o = 16; o > 0; o >>= 1)
            m = fmaxf(m, __shfl_xor_sync(0xffffffffu, m, o));
        if ((tid & 31) == 0) smax[tid >> 5] = m;
    }
    __syncthreads();
    if (tid == 0)
        atomicMax(&g_emax_key[bh], fenc(fmaxf(smax[0], smax[1])));
}

// ---------------- K2 builder iteration (half2 P-build) ----------------
__device__ __forceinline__ void builder_iter(
    float* sm, __half* smh, uint32_t smb, const float* __restrict__ adjs,
    int b, int i0, int half_, int bt, int c4, int rb,
    int h, int jt, float Eh,
    const __half2* rel2, const __half2* rA2, const __half2* rC2,
    float4* cur, float4* nxt)
{
    const int g = h * NJT + jt, buf = g & 1;
    const int bh = b * H + h;
    const int jbase = half_ * JH + jt * TJ;
    {
        const int jn = half_ * JH + ((jt + 1) & 15) * TJ;
        const float* apn = adjs + ((size_t)(b * NN + i0 + rb)) * NN + jn + c4 * 4;
        #pragma unroll
        for (int v = 0; v < 8; v++) nxt[v] = *(const float4*)(apn + (size_t)(v * 8) * NN);
    }
    if (g >= 2) BARS(3 + buf, 256);
    if (bt < 64) {
        float er = g_er[(size_t)bh * NN + jbase + bt];
        float u = er - Eh;
        sm[OFF_ER_F + buf * 192 + bt] = er;
        sm[OFF_ER_F + buf * 192 + 64 + bt] = ex2f(u);
        sm[OFF_ER_F + buf * 192 + 128 + bt] = ex2f(0.1f * u);
    }
    {
        uint32_t hB = smb + OFF_HS_BYTES + buf * HSBUF_BYTES;
        const __half* hsrc = g_hs_h + (size_t)bh * COUT * NN + jbase;
        #pragma unroll
        for (int v = 0; v < 4; v++) {
            int idx = bt + v * 128;
            int d = idx >> 3, j8 = idx & 7;
            cp16(hB + (uint32_t)(d * PSTR + j8 * 8) * 2, hsrc + (size_t)d * NN + j8 * 8);
        }
        CP_COMMIT;
    }
    BARS(5, 128);
    // build P in half2: p = adjmask & (s>0 ? A*B : C*D)
    {
        float4 er4 = *(const float4*)(sm + OFF_ER_F + buf * 192 + c4 * 4);
        float4 B4  = *(const float4*)(sm + OFF_ER_F + buf * 192 + 64 + c4 * 4);
        float4 D4  = *(const float4*)(sm + OFF_ER_F + buf * 192 + 128 + c4 * 4);
        const float* erv = (const float*)&er4;
        const float* Bv  = (const float*)&B4;
        const float* Dv  = (const float*)&D4;
        __half2 er2[2] = {__floats2half2_rn(erv[0], erv[1]), __floats2half2_rn(erv[2], erv[3])};
        __half2 B2[2]  = {__floats2half2_rn(Bv[0],  Bv[1]),  __floats2half2_rn(Bv[2],  Bv[3])};
        __half2 D2[2]  = {__floats2half2_rn(Dv[0],  Dv[1]),  __floats2half2_rn(Dv[2],  Dv[3])};
        const __half2 z2 = __floats2half2_rn(0.f, 0.f);
        __half* sPb = smh + (buf * PBUF_BYTES) / 2;
        #pragma unroll
        for (int v = 0; v < 8; v++) {
            int r = rb + v * 8;
            const float* av = (const float*)&cur[v];
            uint32_t outp[2];
            #pragma unroll
            for (int q = 0; q < 2; q++) {
                __half2 a2 = __floats2half2_rn(av[2 * q], av[2 * q + 1]);
                uint32_t madj = __hgt2_mask(a2, z2);
                __half2 s2 = __hadd2(rel2[v], er2[q]);
                uint32_t msel = __hgt2_mask(s2, z2);
                __half2 AB = __hmul2(rA2[v], B2[q]);
                __half2 CD = __hmul2(rC2[v], D2[q]);
                uint32_t ab = *(uint32_t*)&AB;
                uint32_t cd = *(uint32_t*)&CD;
                outp[q] = ((ab & msel) | (cd & ~msel)) & madj;
            }
            *(uint2*)(sPb + r * PSTR + c4 * 4) = make_uint2(outp[0], outp[1]);
        }
    }
    CP_WAIT0;
    BARA(1 + buf, 256);
}

// ---------------- K2: warp-specialized fp16 mma flash loop ----------------
__global__ __launch_bounds__(256, 2) void k2_attn(const float* __restrict__ adjs) {
    extern __shared__ float sm[];
    __half* smh = (__half*)sm;
    const uint32_t smb = smem_u32(sm);
    const int tid = threadIdx.x, wid = tid >> 5, lane = tid & 31;
    const int i0 = blockIdx.x * TI, half_ = blockIdx.y, b = blockIdx.z;

    for (int idx = tid; idx < 2 * 8 * PSTR; idx += 256) {
        int buf = idx / (8 * PSTR);
        int rem = idx % (8 * PSTR);
        int r8 = rem / PSTR, c = rem % PSTR;
        smh[(OFF_HS_BYTES + buf * HSBUF_BYTES) / 2 + (64 + r8) * PSTR + c] =
            (r8 == 0 && c < 64) ? __float2half(1.f) : __float2half(0.f);
    }
    if (tid < 256) {
        int h = tid >> 6, r = tid & 63;
        int bh = b * H + h;
        float e = g_el[(size_t)bh * NN + i0 + r];
        float E = fdec(g_emax_key[bh]);
        float t = e + E;
        float m = fmaxf(t, 0.1f * t);
        sm[OFF_EL_F + h * 192 + r] = e;
        sm[OFF_EL_F + h * 192 + 64 + r] = ex2f(t - m);
        sm[OFF_EL_F + h * 192 + 128 + r] = ex2f(0.1f * t - m);
    }
    __syncthreads();

    if (wid >= 4) {
        const int bt = tid & 127;
        const int c4 = bt & 15, rb = bt >> 4;
        float4 ajA[8], ajB[8];
        {
            const float* ap0 = adjs + ((size_t)(b * NN + i0 + rb)) * NN + half_ * JH + c4 * 4;
            #pragma unroll
            for (int v = 0; v < 8; v++) ajA[v] = *(const float4*)(ap0 + (size_t)(v * 8) * NN);
        }
        for (int h = 0; h < H; h++) {
            const float Eh = fdec(g_emax_key[b * H + h]);
            __half2 rel2[8], rA2[8], rC2[8];
            #pragma unroll
            for (int v = 0; v < 8; v++) {
                int r = rb + v * 8;
                rel2[v] = __half2half2(__float2half_rn(sm[OFF_EL_F + h * 192 + r]));
                rA2[v]  = __half2half2(__float2half_rn(sm[OFF_EL_F + h * 192 + 64 + r]));
                rC2[v]  = __half2half2(__float2half_rn(sm[OFF_EL_F + h * 192 + 128 + r]));
            }
            #pragma unroll 1
            for (int jp = 0; jp < 8; jp++) {
                builder_iter(sm, smh, smb, adjs, b, i0, half_, bt, c4, rb,
                             h, 2 * jp, Eh, rel2, rA2, rC2, ajA, ajB);
                builder_iter(sm, smh, smb, adjs, b, i0, half_, bt, c4, rb,
                             h, 2 * jp + 1, Eh, rel2, rA2, rC2, ajB, ajA);
            }
        }
    } else {
        const int gid = lane >> 2, tg = lane & 3;
        const uint32_t aRow = (uint32_t)(wid * 16 + (lane & 7) + ((lane >> 3) & 1) * 8);
        const uint32_t aOff = (aRow * PSTR + (lane >> 4) * 8) * 2;
        const uint32_t bRowL = (uint32_t)((lane & 7) + (lane >> 4) * 8);
        const uint32_t bOff = (bRowL * PSTR + ((lane >> 3) & 1) * 8) * 2;
        const int ol = lane & 15;
        const uint32_t oOff = (uint32_t)(((64 + (ol & 7)) * PSTR + ((ol >> 3) & 1) * 8) * 2);
        for (int h = 0; h < H; h++) {
            const int bh = b * H + h;
            float acc[9][4];
            #pragma unroll
            for (int nc = 0; nc < 9; nc++)
                #pragma unroll
                for (int e = 0; e < 4; e++) acc[nc][e] = 0.f;
            for (int jt = 0; jt < NJT; jt++) {
                const int g = h * NJT + jt, buf = g & 1;
                BARS(1 + buf, 256);
                uint32_t pA = smb + buf * PBUF_BYTES + aOff;
                uint32_t hB = smb + OFF_HS_BYTES + buf * HSBUF_BYTES;
                #pragma unroll
                for (int ks = 0; ks < 4; ks++) {
                    uint32_t a[4];
                    ldsm_x4(a, pA); pA += 32;
                    #pragma unroll
                    for (int p2 = 0; p2 < 4; p2++) {
                        uint32_t bb[4];
                        ldsm_x4(bb, hB + bOff + (uint32_t)p2 * (16 * PSTR * 2) + ks * 32);
                        mma_f16(acc[2 * p2], a, bb);
                        mma_f16(acc[2 * p2 + 1], a, bb + 2);
                    }
                    uint32_t oo[2];
                    ldsm_x2(oo, hB + oOff + ks * 32);
                    mma_f16(acc[8], a, oo);
                }
                BARA(3 + buf, 256);
            }
            const int r0 = i0 + wid * 16 + gid;
            float* ob = g_opart[half_] + ((size_t)b * NN) * HD;
            #pragma unroll
            for (int nc = 0; nc < 8; nc++) {
                int col = h * 64 + nc * 8 + 2 * tg;
                float2 v0 = {acc[nc][0], acc[nc][1]};
                float2 v1 = {acc[nc][2], acc[nc][3]};
                *(float2*)(ob + (size_t)r0 * HD + col) = v0;
                *(float2*)(ob + (size_t)(r0 + 8) * HD + col) = v1;
            }
            if (tg == 0) {
                g_lpart[half_][(size_t)bh * NN + r0] = acc[8][0];
                g_lpart[half_][(size_t)bh * NN + r0 + 8] = acc[8][2];
            }
        }
    }
}

// ---------------- K3: combine halves + normalize (8 floats/thread) ----------------
__global__ __launch_bounds__(256) void k3_combine(float* __restrict__ out) {
    int idx = blockIdx.x * 256 + threadIdx.x;
    size_t flat = (size_t)idx * 8;
    int b   = (int)(flat >> 19);
    int rem = (int)(flat & 524287);
    int i = rem >> 8;
    int h = (rem >> 6) & 3;
    size_t li = (size_t)(b * H + h) * NN + i;
    float l = g_lpart[0][li] + g_lpart[1][li];
    float inv = (l > 0.f) ? (1.f / l) : 0.f;
    float4 a0 = *(const float4*)(g_opart[0] + flat);
    float4 a1 = *(const float4*)(g_opart[0] + flat + 4);
    float4 b0 = *(const float4*)(g_opart[1] + flat);
    float4 b1 = *(const float4*)(g_opart[1] + flat + 4);
    float4 w0 = {(a0.x + b0.x) * inv, (a0.y + b0.y) * inv,
                 (a0.z + b0.z) * inv, (a0.w + b0.w) * inv};
    float4 w1 = {(a1.x + b1.x) * inv, (a1.y + b1.y) * inv,
                 (a1.z + b1.z) * inv, (a1.w + b1.w) * inv};
    *(float4*)(out + flat) = w0;
    *(float4*)(out + flat + 4) = w1;
}

extern "C" void kernel_launch(void* const* d_in, const int* in_sizes, int n_in,
                              void* d_out, int out_size) {
    const float* xs   = (const float*)d_in[0];
    const float* adjs = (const float*)d_in[1];
    const float* W1   = (const float*)d_in[2];
    const float* a_l  = (const float*)d_in[3];
    const float* a_r  = (const float*)d_in[4];
    float* out = (float*)d_out;

    cudaFuncSetAttribute(k2_attn, cudaFuncAttributeMaxDynamicSharedMemorySize, SMEM_K2);

    k1_gemm<<<dim3(32, 4, 4), 256>>>(xs, W1, a_l, a_r);
    k2_attn<<<dim3(32, 2, 4), 256, SMEM_K2>>>(adjs);
    k3_combine<<<(BS * NN * HD / 8) / 256, 256>>>(out);
}

// round 16
// speedup vs baseline: 1.2302x; 1.0206x over previous
#include <cuda_runtime.h>
#include <cuda_fp16.h>
#include <cstdint>

#define BS   4
#define NN   2048
#define CIN  128
#define COUT 64
#define H    4
#define HD   256
#define TI   64
#define TJ   64
#define JH   1024
#define NJT  16
#define LOG2E 1.4426950408889634f

// device scratch (allocation-free)
__device__ __half g_hs_h[(size_t)BS * H * COUT * NN];  // [bh][d][n] fp16 (transposed)
__device__ float g_el[BS * H * NN];                    // pre-scaled by log2e
__device__ float g_er[BS * H * NN];                    // pre-scaled by log2e
__device__ unsigned int g_emax_key[BS * H];            // float-ordered key (0-init; idempotent)
__device__ float g_opart[2][(size_t)BS * NN * HD];
__device__ float g_lpart[2][BS * H * NN];

// K2 smem layout
#define PSTR 72
#define PBUF_BYTES  9216
#define HSBUF_BYTES 10368
#define OFF_HS_BYTES 18432
#define OFF_EL_F 10176         // per head {el[64],A[64],C[64]} x4 (floats)
// factor tables (halfs), one-time prologue fill: per head h at byte 44032 + h*6144:
//   er[1024] @ +0, B[1024] @ +2048, D[1024] @ +4096
#define OFF_TBL_BYTES 44032
#define SMEM_K2 68608

__device__ __forceinline__ uint32_t smem_u32(const void* p) {
    uint32_t a;
    asm("{ .reg .u64 t; cvta.to.shared.u64 t, %1; cvt.u32.u64 %0, t; }" : "=r"(a) : "l"(p));
    return a;
}
__device__ __forceinline__ float ex2f(float x) {
    float r;
    asm("ex2.approx.f32 %0, %1;" : "=f"(r) : "f"(x));
    return r;
}
__device__ __forceinline__ unsigned int fenc(float f) {
    unsigned int b = __float_as_uint(f);
    return (b & 0x80000000u) ? ~b : (b | 0x80000000u);
}
__device__ __forceinline__ float fdec(unsigned int k) {
    unsigned int b = (k & 0x80000000u) ? (k ^ 0x80000000u) : ~k;
    return __uint_as_float(b);
}
__device__ __forceinline__ void mma_f16(float* d, const uint32_t* a, const uint32_t* b) {
    asm volatile(
        "mma.sync.aligned.m16n8k16.row.col.f32.f16.f16.f32 "
        "{%0,%1,%2,%3}, {%4,%5,%6,%7}, {%8,%9}, {%0,%1,%2,%3};"
        : "+f"(d[0]), "+f"(d[1]), "+f"(d[2]), "+f"(d[3])
        : "r"(a[0]), "r"(a[1]), "r"(a[2]), "r"(a[3]), "r"(b[0]), "r"(b[1]));
}
__device__ __forceinline__ void ldsm_x4(uint32_t* r, uint32_t addr) {
    asm volatile("ldmatrix.sync.aligned.m8n8.x4.shared.b16 {%0,%1,%2,%3}, [%4];"
                 : "=r"(r[0]), "=r"(r[1]), "=r"(r[2]), "=r"(r[3]) : "r"(addr));
}
__device__ __forceinline__ void ldsm_x2(uint32_t* r, uint32_t addr) {
    asm volatile("ldmatrix.sync.aligned.m8n8.x2.shared.b16 {%0,%1}, [%2];"
                 : "=r"(r[0]), "=r"(r[1]) : "r"(addr));
}
__device__ __forceinline__ void cp16(uint32_t dst, const void* src) {
    asm volatile("cp.async.ca.shared.global [%0], [%1], 16;" :: "r"(dst), "l"(src));
}
#define CP_COMMIT asm volatile("cp.async.commit_group;" ::: "memory")
#define CP_WAIT0  asm volatile("cp.async.wait_group 0;" ::: "memory")
#define BARS(id, n) asm volatile("bar.sync %0, %1;" :: "r"(id), "r"(n) : "memory")
#define BARA(id, n) asm volatile("bar.arrive %0, %1;" :: "r"(id), "r"(n) : "memory")

// ---------------- K1: hs = xs @ W1 (per-head), fp16-T store, el/er, fused emax (R12) ----------------
__global__ __launch_bounds__(256) void k1_gemm(const float* __restrict__ xs,
                                               const float* __restrict__ W1,
                                               const float* __restrict__ a_l,
                                               const float* __restrict__ a_r) {
    const int bx = blockIdx.x, head = blockIdx.y, b = blockIdx.z;
    const int tid = threadIdx.x;
    const int ig = tid >> 4, cg = tid & 15;
    const int r0 = ig * 4, c0 = cg * 4;

    __shared__ float As[32][68];
    __shared__ float Bs[32][68];
    __shared__ float sred[16][64];
    __shared__ float smax[2];

    float acc[4][4] = {};
    const float* xbase = xs + ((size_t)(b * NN + bx * 64)) * CIN;
    const float* wbase = W1 + head * COUT;

    for (int kc = 0; kc < CIN; kc += 32) {
        int lin = tid;
        #pragma unroll
        for (int t = 0; t < 2; t++, lin += 256) {
            int r = lin >> 3, k4 = lin & 7;
            float4 v = *(const float4*)(xbase + r * CIN + kc + k4 * 4);
            As[k4 * 4 + 0][r] = v.x; As[k4 * 4 + 1][r] = v.y;
            As[k4 * 4 + 2][r] = v.z; As[k4 * 4 + 3][r] = v.w;
        }
        lin = tid;
        #pragma unroll
        for (int t = 0; t < 2; t++, lin += 256) {
            int k = lin >> 4, c4 = lin & 15;
            float4 v = *(const float4*)(wbase + (size_t)(kc + k) * HD + c4 * 4);
            *(float4*)&Bs[k][c4 * 4] = v;
        }
        __syncthreads();
        #pragma unroll
        for (int k = 0; k < 32; k++) {
            float4 aq = *(const float4*)&As[k][r0];
            float4 bq = *(const float4*)&Bs[k][c0];
            float ar[4] = {aq.x, aq.y, aq.z, aq.w};
            float br[4] = {bq.x, bq.y, bq.z, bq.w};
            #pragma unroll
            for (int r = 0; r < 4; r++)
                #pragma unroll
                for (int c = 0; c < 4; c++) acc[r][c] += ar[r] * br[c];
        }
        __syncthreads();
    }

    const int bh = b * H + head;
    #pragma unroll
    for (int c = 0; c < 4; c++) {
        __half2 lo = __floats2half2_rn(acc[0][c], acc[1][c]);
        __half2 hi = __floats2half2_rn(acc[2][c], acc[3][c]);
        uint2 w = {*(uint32_t*)&lo, *(uint32_t*)&hi};
        *(uint2*)(g_hs_h + ((size_t)(bh * COUT + c0 + c)) * NN + bx * 64 + r0) = w;
    }
    float pl[4] = {}, pr[4] = {};
    #pragma unroll
    for (int r = 0; r < 4; r++)
        #pragma unroll
        for (int c = 0; c < 4; c++) {
            pl[r] += acc[r][c] * __ldg(a_l + c0 + c);
            pr[r] += acc[r][c] * __ldg(a_r + c0 + c);
        }
    #pragma unroll
    for (int r = 0; r < 4; r++) sred[cg][r0 + r] = pl[r];
    __syncthreads();
    if (tid < 64) {
        float s = 0.f;
        #pragma unroll
        for (int g = 0; g < 16; g++) s += sred[g][tid];
        g_el[(size_t)bh * NN + bx * 64 + tid] = s * LOG2E;
    }
    __syncthreads();
    #pragma unroll
    for (int r = 0; r < 4; r++) sred[cg][r0 + r] = pr[r];
    __syncthreads();
    if (tid < 64) {
        float s = 0.f;
        #pragma unroll
        for (int g = 0; g < 16; g++) s += sred[g][tid];
        float es = s * LOG2E;
        g_er[(size_t)bh * NN + bx * 64 + tid] = es;
        float m = es;
        #pragma unroll
        for (int o = 16; o > 0; o >>= 1)
            m = fmaxf(m, __shfl_xor_sync(0xffffffffu, m, o));
        if ((tid & 31) == 0) smax[tid >> 5] = m;
    }
    __syncthreads();
    if (tid == 0)
        atomicMax(&g_emax_key[bh], fenc(fmaxf(smax[0], smax[1])));
}

// ---------------- K2 builder iteration (table-driven half2 P-build) ----------------
__device__ __forceinline__ void builder_iter(
    __half* smh, uint32_t smb, const float* __restrict__ adjs,
    int b, int i0, int half_, int bt, int c4, int rb,
    int h, int jt,
    const __half2* rel2, const __half2* rA2, const __half2* rC2,
    float4* cur, float4* nxt)
{
    const int g = h * NJT + jt, buf = g & 1;
    const int bh = b * H + h;
    const int jbase = half_ * JH + jt * TJ;
    {
        const int jn = half_ * JH + ((jt + 1) & 15) * TJ;
        const float* apn = adjs + ((size_t)(b * NN + i0 + rb)) * NN + jn + c4 * 4;
        #pragma unroll
        for (int v = 0; v < 8; v++) nxt[v] = *(const float4*)(apn + (size_t)(v * 8) * NN);
    }
    if (g >= 2) BARS(3 + buf, 256);
    {
        uint32_t hB = smb + OFF_HS_BYTES + buf * HSBUF_BYTES;
        const __half* hsrc = g_hs_h + (size_t)bh * COUT * NN + jbase;
        #pragma unroll
        for (int v = 0; v < 4; v++) {
            int idx = bt + v * 128;
            int d = idx >> 3, j8 = idx & 7;
            cp16(hB + (uint32_t)(d * PSTR + j8 * 8) * 2, hsrc + (size_t)d * NN + j8 * 8);
        }
        CP_COMMIT;
    }
    // build P in half2 from precomputed tables: p = adjmask & (s>0 ? A*B : C*D)
    {
        const __half* tbl = smh + OFF_TBL_BYTES / 2 + h * 3072 + jt * 64 + c4 * 4;
        uint2 eru = *(const uint2*)(tbl);
        uint2 Bu  = *(const uint2*)(tbl + 1024);
        uint2 Du  = *(const uint2*)(tbl + 2048);
        __half2 er2[2] = {*(__half2*)&eru.x, *(__half2*)&eru.y};
        __half2 B2[2]  = {*(__half2*)&Bu.x,  *(__half2*)&Bu.y};
        __half2 D2[2]  = {*(__half2*)&Du.x,  *(__half2*)&Du.y};
        const __half2 z2 = __floats2half2_rn(0.f, 0.f);
        __half* sPb = smh + (buf * PBUF_BYTES) / 2;
        #pragma unroll
        for (int v = 0; v < 8; v++) {
            int r = rb + v * 8;
            const float* av = (const float*)&cur[v];
            uint32_t outp[2];
            #pragma unroll
            for (int q = 0; q < 2; q++) {
                __half2 a2 = __floats2half2_rn(av[2 * q], av[2 * q + 1]);
                uint32_t madj = __hgt2_mask(a2, z2);
                __half2 s2 = __hadd2(rel2[v], er2[q]);
                uint32_t msel = __hgt2_mask(s2, z2);
                __half2 AB = __hmul2(rA2[v], B2[q]);
                __half2 CD = __hmul2(rC2[v], D2[q]);
                uint32_t ab = *(uint32_t*)&AB;
                uint32_t cd = *(uint32_t*)&CD;
                outp[q] = ((ab & msel) | (cd & ~msel)) & madj;
            }
            *(uint2*)(sPb + r * PSTR + c4 * 4) = make_uint2(outp[0], outp[1]);
        }
    }
    CP_WAIT0;
    BARA(1 + buf, 256);
}

// ---------------- K2: warp-specialized fp16 mma flash loop ----------------
__global__ __launch_bounds__(256, 2) void k2_attn(const float* __restrict__ adjs) {
    extern __shared__ float sm[];
    __half* smh = (__half*)sm;
    const uint32_t smb = smem_u32(sm);
    const int tid = threadIdx.x, wid = tid >> 5, lane = tid & 31;
    const int i0 = blockIdx.x * TI, half_ = blockIdx.y, b = blockIdx.z;

    // ones rows (64..71) of both HS buffers
    for (int idx = tid; idx < 2 * 8 * PSTR; idx += 256) {
        int buf = idx / (8 * PSTR);
        int rem = idx % (8 * PSTR);
        int r8 = rem / PSTR, c = rem % PSTR;
        smh[(OFF_HS_BYTES + buf * HSBUF_BYTES) / 2 + (64 + r8) * PSTR + c] =
            (r8 == 0 && c < 64) ? __float2half(1.f) : __float2half(0.f);
    }
    // per-head el / A / C (floats, for row factors)
    if (tid < 256) {
        int h = tid >> 6, r = tid & 63;
        int bh = b * H + h;
        float e = g_el[(size_t)bh * NN + i0 + r];
        float E = fdec(g_emax_key[bh]);
        float t = e + E;
        float m = fmaxf(t, 0.1f * t);
        sm[OFF_EL_F + h * 192 + r] = e;
        sm[OFF_EL_F + h * 192 + 64 + r] = ex2f(t - m);
        sm[OFF_EL_F + h * 192 + 128 + r] = ex2f(0.1f * t - m);
    }
    // factor tables: per (h, j-local) {er, B, D} as fp16 — one-time fill
    for (int idx = tid; idx < H * 1024; idx += 256) {
        int h = idx >> 10, jl = idx & 1023;
        int bh = b * H + h;
        float er = g_er[(size_t)bh * NN + half_ * JH + jl];
        float u = er - fdec(g_emax_key[bh]);
        __half* tb = smh + OFF_TBL_BYTES / 2 + h * 3072;
        tb[jl] = __float2half_rn(er);
        tb[1024 + jl] = __float2half_rn(ex2f(u));
        tb[2048 + jl] = __float2half_rn(ex2f(0.1f * u));
    }
    __syncthreads();

    if (wid >= 4) {
        // ---------------- builders ----------------
        const int bt = tid & 127;
        const int c4 = bt & 15, rb = bt >> 4;
        float4 ajA[8], ajB[8];
        {
            const float* ap0 = adjs + ((size_t)(b * NN + i0 + rb)) * NN + half_ * JH + c4 * 4;
            #pragma unroll
            for (int v = 0; v < 8; v++) ajA[v] = *(const float4*)(ap0 + (size_t)(v * 8) * NN);
        }
        for (int h = 0; h < H; h++) {
            __half2 rel2[8], rA2[8], rC2[8];
            #pragma unroll
            for (int v = 0; v < 8; v++) {
                int r = rb + v * 8;
                rel2[v] = __half2half2(__float2half_rn(sm[OFF_EL_F + h * 192 + r]));
                rA2[v]  = __half2half2(__float2half_rn(sm[OFF_EL_F + h * 192 + 64 + r]));
                rC2[v]  = __half2half2(__float2half_rn(sm[OFF_EL_F + h * 192 + 128 + r]));
            }
            #pragma unroll 1
            for (int jp = 0; jp < 8; jp++) {
                builder_iter(smh, smb, adjs, b, i0, half_, bt, c4, rb,
                             h, 2 * jp, rel2, rA2, rC2, ajA, ajB);
                builder_iter(smh, smb, adjs, b, i0, half_, bt, c4, rb,
                             h, 2 * jp + 1, rel2, rA2, rC2, ajB, ajA);
            }
        }
    } else {
        // ---------------- consumers ----------------
        const int gid = lane >> 2, tg = lane & 3;
        const uint32_t aRow = (uint32_t)(wid * 16 + (lane & 7) + ((lane >> 3) & 1) * 8);
        const uint32_t aOff = (aRow * PSTR + (lane >> 4) * 8) * 2;
        const uint32_t bRowL = (uint32_t)((lane & 7) + (lane >> 4) * 8);
        const uint32_t bOff = (bRowL * PSTR + ((lane >> 3) & 1) * 8) * 2;
        const int ol = lane & 15;
        const uint32_t oOff = (uint32_t)(((64 + (ol & 7)) * PSTR + ((ol >> 3) & 1) * 8) * 2);
        for (int h = 0; h < H; h++) {
            const int bh = b * H + h;
            float acc[9][4];
            #pragma unroll
            for (int nc = 0; nc < 9; nc++)
                #pragma unroll
                for (int e = 0; e < 4; e++) acc[nc][e] = 0.f;
            for (int jt = 0; jt < NJT; jt++) {
                const int g = h * NJT + jt, buf = g & 1;
                BARS(1 + buf, 256);
                uint32_t pA = smb + buf * PBUF_BYTES + aOff;
                uint32_t hB = smb + OFF_HS_BYTES + buf * HSBUF_BYTES;
                #pragma unroll
                for (int ks = 0; ks < 4; ks++) {
                    uint32_t a[4];
                    ldsm_x4(a, pA); pA += 32;
                    #pragma unroll
                    for (int p2 = 0; p2 < 4; p2++) {
                        uint32_t bb[4];
                        ldsm_x4(bb, hB + bOff + (uint32_t)p2 * (16 * PSTR * 2) + ks * 32);
                        mma_f16(acc[2 * p2], a, bb);
                        mma_f16(acc[2 * p2 + 1], a, bb + 2);
                    }
                    uint32_t oo[2];
                    ldsm_x2(oo, hB + oOff + ks * 32);
                    mma_f16(acc[8], a, oo);
                }
                BARA(3 + buf, 256);
            }
            const int r0 = i0 + wid * 16 + gid;
            float* ob = g_opart[half_] + ((size_t)b * NN) * HD;
            #pragma unroll
            for (int nc = 0; nc < 8; nc++) {
                int col = h * 64 + nc * 8 + 2 * tg;
                float2 v0 = {acc[nc][0], acc[nc][1]};
                float2 v1 = {acc[nc][2], acc[nc][3]};
                *(float2*)(ob + (size_t)r0 * HD + col) = v0;
                *(float2*)(ob + (size_t)(r0 + 8) * HD + col) = v1;
            }
            if (tg == 0) {
                g_lpart[half_][(size_t)bh * NN + r0] = acc[8][0];
                g_lpart[half_][(size_t)bh * NN + r0 + 8] = acc[8][2];
            }
        }
    }
}

// ---------------- K3: combine halves + normalize (8 floats/thread) ----------------
__global__ __launch_bounds__(256) void k3_combine(float* __restrict__ out) {
    int idx = blockIdx.x * 256 + threadIdx.x;
    size_t flat = (size_t)idx * 8;
    int b   = (int)(flat >> 19);
    int rem = (int)(flat & 524287);
    int i = rem >> 8;
    int h = (rem >> 6) & 3;
    size_t li = (size_t)(b * H + h) * NN + i;
    float l = g_lpart[0][li] + g_lpart[1][li];
    float inv = (l > 0.f) ? (1.f / l) : 0.f;
    float4 a0 = *(const float4*)(g_opart[0] + flat);
    float4 a1 = *(const float4*)(g_opart[0] + flat + 4);
    float4 b0 = *(const float4*)(g_opart[1] + flat);
    float4 b1 = *(const float4*)(g_opart[1] + flat + 4);
    float4 w0 = {(a0.x + b0.x) * inv, (a0.y + b0.y) * inv,
                 (a0.z + b0.z) * inv, (a0.w + b0.w) * inv};
    float4 w1 = {(a1.x + b1.x) * inv, (a1.y + b1.y) * inv,
                 (a1.z + b1.z) * inv, (a1.w + b1.w) * inv};
    *(float4*)(out + flat) = w0;
    *(float4*)(out + flat + 4) = w1;
}

extern "C" void kernel_launch(void* const* d_in, const int* in_sizes, int n_in,
                              void* d_out, int out_size) {
    const float* xs   = (const float*)d_in[0];
    const float* adjs = (const float*)d_in[1];
    const float* W1   = (const float*)d_in[2];
    const float* a_l  = (const float*)d_in[3];
    const float* a_r  = (const float*)d_in[4];
    float* out = (float*)d_out;

    cudaFuncSetAttribute(k2_attn, cudaFuncAttributeMaxDynamicSharedMemorySize, SMEM_K2);

    k1_gemm<<<dim3(32, 4, 4), 256>>>(xs, W1, a_l, a_r);
    k2_attn<<<dim3(32, 2, 4), 256, SMEM_K2>>>(adjs);
    k3_combine<<<(BS * NN * HD / 8) / 256, 256>>>(out);
}